// round 8
// baseline (speedup 1.0000x reference)
#include <cuda_runtime.h>

// loss = mean(|preds*mask - targets|) + 0.1 * mean((pd - td)^2)
//   mask = (targets != 0), bones i -> (i+1) % 50, dir = diff/(||diff||+1e-8)
// preds/targets: [128, 1024, 150] fp32; scalar fp32 output.

#define ROW_ELEMS 150
#define N_BONES 50
#define TOTAL_ROWS (128 * 1024)
#define THREADS 256
#define WARPS_PER_BLOCK (THREADS / 32)
#define BLOCKS_PER_SM 4
#define LAUNCH_BLOCKS (148 * BLOCKS_PER_SM)           // 592 — all resident, one wave
#define TOTAL_WARPS (LAUNCH_BLOCKS * WARPS_PER_BLOCK) // 4736
#define ROWS_PER_WTILE 2
#define WTILE_ELEMS (ROWS_PER_WTILE * ROW_ELEMS)      // 300 floats (75 float4)
#define WTILE_VEC4 (WTILE_ELEMS / 4)                  // 75
#define NUM_WTILES (TOTAL_ROWS / ROWS_PER_WTILE)      // 65536

__device__ float2 g_partials[LAUNCH_BLOCKS];
__device__ unsigned int g_count;                      // zero-init; self-resets

__device__ __forceinline__ void load_tile(
    const float* __restrict__ preds, const float* __restrict__ targets,
    int wt, int lane, bool hasC,
    float4& pA, float4& pB, float4& pC,
    float4& tA, float4& tB, float4& tC)
{
    const long long base4 = (long long)wt * WTILE_VEC4;
    const float4* __restrict__ p4 = (const float4*)preds + base4;
    const float4* __restrict__ t4 = (const float4*)targets + base4;
    pA = p4[lane];        tA = t4[lane];
    pB = p4[lane + 32];   tB = t4[lane + 32];
    if (hasC) { pC = p4[lane + 64]; tC = t4[lane + 64]; }
}

__device__ __forceinline__ void mask_l1_store(
    const float4& p, const float4& t, float& l1,
    float4* pm_s4, float4* t_s4, int idx)
{
    float4 pm;
    pm.x = (t.x != 0.0f) ? p.x : 0.0f;
    pm.y = (t.y != 0.0f) ? p.y : 0.0f;
    pm.z = (t.z != 0.0f) ? p.z : 0.0f;
    pm.w = (t.w != 0.0f) ? p.w : 0.0f;
    l1 += fabsf(pm.x - t.x) + fabsf(pm.y - t.y)
        + fabsf(pm.z - t.z) + fabsf(pm.w - t.w);
    pm_s4[idx] = pm;
    t_s4[idx] = t;
}

__global__ __launch_bounds__(THREADS, BLOCKS_PER_SM) void loss_fused(
    const float* __restrict__ preds,
    const float* __restrict__ targets,
    float* __restrict__ out)
{
    // Per-warp private SMEM slices: masked preds + targets, 300 floats each.
    __shared__ float pm_sh[WARPS_PER_BLOCK][WTILE_ELEMS];
    __shared__ float t_sh[WARPS_PER_BLOCK][WTILE_ELEMS];

    const int tid = threadIdx.x;
    const int wid = tid >> 5;
    const int lane = tid & 31;
    const int gwarp = blockIdx.x * WARPS_PER_BLOCK + wid;
    const bool hasC = (lane < WTILE_VEC4 - 64);       // lanes 0..10

    float* pm_s = pm_sh[wid];
    float* t_s = t_sh[wid];
    float4* pm_s4 = (float4*)pm_s;
    float4* t_s4 = (float4*)t_s;

    float l1 = 0.0f;
    float mse = 0.0f;

    // Software pipeline: prefetch tile n+1 before consuming tile n.
    float4 cpA, cpB, cpC, ctA, ctB, ctC;      // current
    if (gwarp < NUM_WTILES)
        load_tile(preds, targets, gwarp, lane, hasC, cpA, cpB, cpC, ctA, ctB, ctC);

    for (int wt = gwarp; wt < NUM_WTILES; wt += TOTAL_WARPS) {
        // ---- prefetch next tile (loads in flight while we compute) ----
        const int nxt = wt + TOTAL_WARPS;
        float4 npA, npB, npC, ntA, ntB, ntC;
        if (nxt < NUM_WTILES)
            load_tile(preds, targets, nxt, lane, hasC, npA, npB, npC, ntA, ntB, ntC);

        __syncwarp();   // SMEM reuse guard: prior bone pass done before overwrite

        // ---- mask + L1 + SMEM store from current registers ----
        mask_l1_store(cpA, ctA, l1, pm_s4, t_s4, lane);
        mask_l1_store(cpB, ctB, l1, pm_s4, t_s4, lane + 32);
        if (hasC) mask_l1_store(cpC, ctC, l1, pm_s4, t_s4, lane + 64);

        __syncwarp();

        // ---- bone pass: 2 rows * 50 bones = 100 tasks over 32 lanes ----
        #pragma unroll
        for (int tk = 0; tk < 4; tk++) {
            int task = lane + tk * 32;
            if (task >= ROWS_PER_WTILE * N_BONES) break;
            int r = (task >= N_BONES) ? 1 : 0;
            int i = task - r * N_BONES;
            int j1 = (i + 1 == N_BONES) ? 0 : (i + 1);
            const float* __restrict__ pr = pm_s + r * ROW_ELEMS;
            const float* __restrict__ tr = t_s + r * ROW_ELEMS;

            float pdv[3], tdv[3], m[3];
            float pl2 = 0.0f, tl2 = 0.0f;
            #pragma unroll
            for (int d = 0; d < 3; d++) {
                float t0 = tr[i * 3 + d];
                float t1 = tr[j1 * 3 + d];
                float pdiff = pr[i * 3 + d] - pr[j1 * 3 + d];  // already masked
                float tdiff = t0 - t1;
                pdv[d] = pdiff;
                tdv[d] = tdiff;
                m[d] = (t0 != 0.0f) ? 1.0f : 0.0f;
                pl2 += pdiff * pdiff;
                tl2 += tdiff * tdiff;
            }
            // 1/(sqrt(x)+1e-8) ≈ rsqrt(x) to ~1e-8 rel; exact-0 guarded (ref -> 0).
            float pinv = (pl2 > 0.0f) ? rsqrtf(pl2) : 0.0f;
            float tinv = (tl2 > 0.0f) ? rsqrtf(tl2) : 0.0f;
            #pragma unroll
            for (int d = 0; d < 3; d++) {
                float x = (pdv[d] * pinv - tdv[d] * tinv) * m[d];
                mse += x * x;
            }
        }

        // ---- rotate buffers ----
        cpA = npA; cpB = npB; cpC = npC;
        ctA = ntA; ctB = ntB; ctC = ntC;
    }

    // ---- deterministic block reduction ----
    __shared__ float s_l1[THREADS];
    __shared__ float s_mse[THREADS];
    s_l1[tid] = l1;
    s_mse[tid] = mse;
    __syncthreads();
    #pragma unroll
    for (int s = THREADS / 2; s > 0; s >>= 1) {
        if (tid < s) {
            s_l1[tid] += s_l1[tid + s];
            s_mse[tid] += s_mse[tid + s];
        }
        __syncthreads();
    }

    // ---- last-arriving block does the final reduction (fixed order) ----
    __shared__ bool s_last;
    if (tid == 0) {
        g_partials[blockIdx.x] = make_float2(s_l1[0], s_mse[0]);
        __threadfence();
        unsigned int v = atomicAdd(&g_count, 1u);
        s_last = (v == LAUNCH_BLOCKS - 1);
    }
    __syncthreads();

    if (s_last) {
        __shared__ double d_l1[THREADS];
        __shared__ double d_mse[THREADS];
        double a = 0.0, b = 0.0;
        #pragma unroll
        for (int k = tid; k < LAUNCH_BLOCKS; k += THREADS) {
            float2 v = __ldcg(&g_partials[k]);
            a += (double)v.x;
            b += (double)v.y;
        }
        d_l1[tid] = a;
        d_mse[tid] = b;
        __syncthreads();
        #pragma unroll
        for (int s = THREADS / 2; s > 0; s >>= 1) {
            if (tid < s) {
                d_l1[tid] += d_l1[tid + s];
                d_mse[tid] += d_mse[tid + s];
            }
            __syncthreads();
        }
        if (tid == 0) {
            const double TOT = (double)TOTAL_ROWS * (double)ROW_ELEMS;
            out[0] = (float)(d_l1[0] / TOT + 0.1 * (d_mse[0] / TOT));
            g_count = 0;   // reset for next graph replay
        }
    }
}

extern "C" void kernel_launch(void* const* d_in, const int* in_sizes, int n_in,
                              void* d_out, int out_size)
{
    const float* preds   = (const float*)d_in[0];
    const float* targets = (const float*)d_in[1];
    float* out = (float*)d_out;

    loss_fused<<<LAUNCH_BLOCKS, THREADS>>>(preds, targets, out);
}